// round 1
// baseline (speedup 1.0000x reference)
#include <cuda_runtime.h>
#include <cstdint>

#define NN   100000
#define EE   300000
#define ETOT 400000   // EE + NN self loops
#define GG   4000
#define INC  9
#define HIDC 128
#define NH   4
#define HC1  512      // NH*HIDC

typedef unsigned long long ull;

// ---------------- scratch (device globals; no allocation allowed) ----------------
__device__ float g_act1[(size_t)NN * HC1];   // 205 MB  elu(layer1 out)
__device__ float g_h2  [(size_t)NN * HIDC];  // 51 MB   layer2 pre-agg projection
__device__ float g_act2[(size_t)NN * HIDC];  // 51 MB   elu(layer2 out)
__device__ float g_xagg[(size_t)NN * NH * INC]; // 14.4 MB  per-head alpha-weighted x sums
__device__ float g_as1[NN * NH], g_ad1[NN * NH];
__device__ float g_as2[NN],      g_ad2[NN];
__device__ float g_asv[NH * INC], g_adv[NH * INC]; // projected attention vectors (36 each)
__device__ int   g_deg[NN];
__device__ int   g_rowoff[NN + 1];
__device__ int   g_cursor[NN];
__device__ int   g_csrc[ETOT];
__device__ float g_cnt[GG];

__device__ __forceinline__ float lrelu(float x) { return x > 0.f ? x : 0.2f * x; }
__device__ __forceinline__ float eluf (float x) { return x > 0.f ? x : expm1f(x); }

// ---------------- 0: zero out + counters ----------------
__global__ void k_zero(float* __restrict__ out) {
    int i = blockIdx.x * blockDim.x + threadIdx.x;
    if (i < GG * HIDC) out[i] = 0.f;
    if (i < NN)        g_deg[i] = 0;
    if (i < GG)        g_cnt[i] = 0.f;
}

// ---------------- 1: dst histogram (edges + self loops) ----------------
__global__ void k_hist(const int* __restrict__ ei) {
    int i = blockIdx.x * blockDim.x + threadIdx.x;
    if (i >= ETOT) return;
    int d = (i < EE) ? ei[EE + i] : (i - EE);
    atomicAdd(&g_deg[d], 1);
}

// ---------------- 2: exclusive scan (single block) ----------------
__global__ void k_scan() {
    const int T = 1024, CH = (NN + T - 1) / T;  // 98
    __shared__ int sh[T];
    int t = threadIdx.x;
    int base = t * CH;
    int s = 0;
    for (int i = 0; i < CH; i++) { int idx = base + i; if (idx < NN) s += g_deg[idx]; }
    sh[t] = s; __syncthreads();
    for (int o = 1; o < T; o <<= 1) {
        int v = (t >= o) ? sh[t - o] : 0;
        __syncthreads();
        sh[t] += v;
        __syncthreads();
    }
    int run = sh[t] - s;  // exclusive
    for (int i = 0; i < CH; i++) {
        int idx = base + i;
        if (idx < NN) { int d = g_deg[idx]; g_rowoff[idx] = run; g_cursor[idx] = run; run += d; }
    }
    if (t == T - 1) g_rowoff[NN] = run;
}

// ---------------- 3: scatter into CSR ----------------
__global__ void k_scatter(const int* __restrict__ ei) {
    int i = blockIdx.x * blockDim.x + threadIdx.x;
    if (i >= ETOT) return;
    int s, d;
    if (i < EE) { s = ei[i]; d = ei[EE + i]; } else { s = d = i - EE; }
    int pos = atomicAdd(&g_cursor[d], 1);
    g_csrc[pos] = s;
}

// ---------------- 4: project attention vectors into input space ----------------
// asv[h][k] = sum_c W1[k, h*128+c] * a_src1[h,c]   (alpha_s[n,h] = x[n] . asv[h])
__global__ void k_prevec(const float* __restrict__ W1,
                         const float* __restrict__ a_src1,
                         const float* __restrict__ a_dst1) {
    int t = threadIdx.x;
    if (t >= NH * INC) return;
    int h = t / INC, k = t % INC;
    float s = 0.f, d = 0.f;
    const float* wrow = W1 + k * HC1 + h * HIDC;
    const float* as = a_src1 + h * HIDC;
    const float* ad = a_dst1 + h * HIDC;
    for (int c = 0; c < HIDC; c++) { float w = wrow[c]; s += w * as[c]; d += w * ad[c]; }
    g_asv[t] = s; g_adv[t] = d;
}

// ---------------- 5: per-node attention scalars (layer 1) ----------------
__global__ void k_alpha1(const float* __restrict__ x) {
    int n = blockIdx.x * blockDim.x + threadIdx.x;
    if (n >= NN) return;
    float xr[INC];
#pragma unroll
    for (int k = 0; k < INC; k++) xr[k] = x[n * INC + k];
    float4 s, d;
    float sv[NH], dv[NH];
#pragma unroll
    for (int h = 0; h < NH; h++) {
        float a = 0.f, b = 0.f;
#pragma unroll
        for (int k = 0; k < INC; k++) { a += xr[k] * g_asv[h * INC + k]; b += xr[k] * g_adv[h * INC + k]; }
        sv[h] = a; dv[h] = b;
    }
    s = make_float4(sv[0], sv[1], sv[2], sv[3]);
    d = make_float4(dv[0], dv[1], dv[2], dv[3]);
    *(float4*)&g_as1[n * 4] = s;
    *(float4*)&g_ad1[n * 4] = d;
}

// ---------------- 6: layer-1 aggregation in input space (thread per node) ----------------
__global__ void k_agg1(const float* __restrict__ x) {
    int v = blockIdx.x * blockDim.x + threadIdx.x;
    if (v >= NN) return;
    int e0 = g_rowoff[v], e1 = g_rowoff[v + 1];
    float4 adv = *(const float4*)&g_ad1[v * 4];
    float m[NH] = {-1e30f, -1e30f, -1e30f, -1e30f};
    for (int e = e0; e < e1; e++) {
        int s = g_csrc[e];
        float4 as = *(const float4*)&g_as1[s * 4];
        float l0 = lrelu(as.x + adv.x), l1 = lrelu(as.y + adv.y);
        float l2 = lrelu(as.z + adv.z), l3 = lrelu(as.w + adv.w);
        m[0] = fmaxf(m[0], l0); m[1] = fmaxf(m[1], l1);
        m[2] = fmaxf(m[2], l2); m[3] = fmaxf(m[3], l3);
    }
    float z[NH] = {0.f, 0.f, 0.f, 0.f};
    float acc[NH][INC];
#pragma unroll
    for (int h = 0; h < NH; h++)
#pragma unroll
        for (int k = 0; k < INC; k++) acc[h][k] = 0.f;
    for (int e = e0; e < e1; e++) {
        int s = g_csrc[e];
        float4 as = *(const float4*)&g_as1[s * 4];
        float w[NH];
        w[0] = __expf(lrelu(as.x + adv.x) - m[0]);
        w[1] = __expf(lrelu(as.y + adv.y) - m[1]);
        w[2] = __expf(lrelu(as.z + adv.z) - m[2]);
        w[3] = __expf(lrelu(as.w + adv.w) - m[3]);
        z[0] += w[0]; z[1] += w[1]; z[2] += w[2]; z[3] += w[3];
        const float* xp = x + (size_t)s * INC;
        float xv[INC];
#pragma unroll
        for (int k = 0; k < INC; k++) xv[k] = __ldg(xp + k);
#pragma unroll
        for (int h = 0; h < NH; h++)
#pragma unroll
            for (int k = 0; k < INC; k++) acc[h][k] += w[h] * xv[k];
    }
#pragma unroll
    for (int h = 0; h < NH; h++) {
        float inv = 1.f / (z[h] + 1e-16f);
#pragma unroll
        for (int k = 0; k < INC; k++) g_xagg[(size_t)v * 36 + h * INC + k] = acc[h][k] * inv;
    }
}

// ---------------- 7: layer-1 "deferred" GEMM  act1 = elu(xagg @ W1 + b1) ----------------
// 128 threads/block, thread t owns 4 contiguous cols c0=4t; warp w -> head w.
#define G1B_NPB 64
__global__ __launch_bounds__(128) void k_gemm1b(const float* __restrict__ W1,
                                                const float* __restrict__ b1) {
    int t = threadIdx.x;
    int c0 = t * 4;
    int h = c0 >> 7;   // head, uniform per warp
    float4 wr[INC];
#pragma unroll
    for (int k = 0; k < INC; k++) wr[k] = *(const float4*)&W1[k * HC1 + c0];
    float4 bv = *(const float4*)&b1[c0];
    int n0 = blockIdx.x * G1B_NPB;
    int n1 = min(NN, n0 + G1B_NPB);
    for (int n = n0; n < n1; n++) {
        const float* xa = &g_xagg[(size_t)n * 36 + h * INC];
        float4 acc = make_float4(0.f, 0.f, 0.f, 0.f);
#pragma unroll
        for (int k = 0; k < INC; k++) {
            float xv = xa[k];
            acc.x += xv * wr[k].x; acc.y += xv * wr[k].y;
            acc.z += xv * wr[k].z; acc.w += xv * wr[k].w;
        }
        acc.x = eluf(acc.x + bv.x); acc.y = eluf(acc.y + bv.y);
        acc.z = eluf(acc.z + bv.z); acc.w = eluf(acc.w + bv.w);
        *(float4*)&g_act1[(size_t)n * HC1 + c0] = acc;
    }
}

// ---------------- 8: main GEMM  h2 = act1 @ W2   (128x128x16 tiles, f32x2 FMA) ----------------
__global__ __launch_bounds__(256) void k_gemm2(const float* __restrict__ W2) {
    __shared__ float sA[16][128];
    __shared__ float sB[16][132];   // padded row (16B-aligned stride)
    int bm = blockIdx.x * 128;
    int tid = threadIdx.x;
    int tx = tid & 15, ty = tid >> 4;
    ull acc[8][4];
#pragma unroll
    for (int i = 0; i < 8; i++)
#pragma unroll
        for (int j = 0; j < 4; j++) acc[i][j] = 0ull;

    for (int k0 = 0; k0 < HC1; k0 += 16) {
#pragma unroll
        for (int i = 0; i < 2; i++) {
            int f = tid + (i << 8);
            int r = f >> 2, kc = (f & 3) << 2;
            int row = bm + r;
            float4 v = make_float4(0.f, 0.f, 0.f, 0.f);
            if (row < NN) v = *(const float4*)&g_act1[(size_t)row * HC1 + k0 + kc];
            sA[kc + 0][r] = v.x; sA[kc + 1][r] = v.y;
            sA[kc + 2][r] = v.z; sA[kc + 3][r] = v.w;
        }
#pragma unroll
        for (int i = 0; i < 2; i++) {
            int f = tid + (i << 8);
            int r = f >> 5, nc = (f & 31) << 2;
            *(float4*)&sB[r][nc] = *(const float4*)&W2[(k0 + r) * HIDC + nc];
        }
        __syncthreads();
#pragma unroll
        for (int k = 0; k < 16; k++) {
            ull a2[8], b2[4];
#pragma unroll
            for (int i = 0; i < 8; i++) {
                unsigned ai = __float_as_uint(sA[k][ty * 8 + i]);
                asm("mov.b64 %0, {%1, %1};" : "=l"(a2[i]) : "r"(ai));
            }
#pragma unroll
            for (int j = 0; j < 4; j++)
                b2[j] = *reinterpret_cast<const ull*>(&sB[k][tx * 8 + j * 2]);
#pragma unroll
            for (int i = 0; i < 8; i++)
#pragma unroll
                for (int j = 0; j < 4; j++)
                    asm("fma.rn.f32x2 %0, %1, %2, %0;" : "+l"(acc[i][j]) : "l"(a2[i]), "l"(b2[j]));
        }
        __syncthreads();
    }
#pragma unroll
    for (int i = 0; i < 8; i++) {
        int row = bm + ty * 8 + i;
        if (row >= NN) continue;
#pragma unroll
        for (int j = 0; j < 4; j++) {
            union { ull u; float2 f; } cvt; cvt.u = acc[i][j];
            *(float2*)&g_h2[(size_t)row * HIDC + tx * 8 + j * 2] = cvt.f;
        }
    }
}

// ---------------- 9: layer-2 attention scalars (warp per node) ----------------
__global__ void k_alpha2(const float* __restrict__ a_src2, const float* __restrict__ a_dst2) {
    int gw = (blockIdx.x * blockDim.x + threadIdx.x) >> 5;
    int lane = threadIdx.x & 31;
    if (gw >= NN) return;
    float4 hv = *(const float4*)&g_h2[(size_t)gw * HIDC + lane * 4];
    float4 sa = *(const float4*)&a_src2[lane * 4];
    float4 da = *(const float4*)&a_dst2[lane * 4];
    float ps = hv.x * sa.x + hv.y * sa.y + hv.z * sa.z + hv.w * sa.w;
    float pd = hv.x * da.x + hv.y * da.y + hv.z * da.z + hv.w * da.w;
#pragma unroll
    for (int o = 16; o >= 1; o >>= 1) {
        ps += __shfl_xor_sync(0xffffffffu, ps, o);
        pd += __shfl_xor_sync(0xffffffffu, pd, o);
    }
    if (lane == 0) { g_as2[gw] = ps; g_ad2[gw] = pd; }
}

// ---------------- 10: layer-2 aggregation (warp per node) ----------------
__global__ void k_agg2(const float* __restrict__ b2) {
    int v = (blockIdx.x * blockDim.x + threadIdx.x) >> 5;
    int lane = threadIdx.x & 31;
    if (v >= NN) return;
    int e0 = g_rowoff[v], e1 = g_rowoff[v + 1];
    float ad = g_ad2[v];
    float m = -1e30f;
    for (int e = e0; e < e1; e++) {
        int s = g_csrc[e];
        m = fmaxf(m, lrelu(g_as2[s] + ad));
    }
    float z = 0.f;
    float4 acc = make_float4(0.f, 0.f, 0.f, 0.f);
    for (int e = e0; e < e1; e++) {
        int s = g_csrc[e];
        float w = __expf(lrelu(g_as2[s] + ad) - m);
        z += w;
        float4 hv = *(const float4*)&g_h2[(size_t)s * HIDC + lane * 4];
        acc.x += w * hv.x; acc.y += w * hv.y; acc.z += w * hv.z; acc.w += w * hv.w;
    }
    float inv = 1.f / (z + 1e-16f);
    float4 bv = *(const float4*)&b2[lane * 4];
    float4 o;
    o.x = eluf(acc.x * inv + bv.x); o.y = eluf(acc.y * inv + bv.y);
    o.z = eluf(acc.z * inv + bv.z); o.w = eluf(acc.w * inv + bv.w);
    *(float4*)&g_act2[(size_t)v * HIDC + lane * 4] = o;
}

// ---------------- 11: pooled sums (batch is sorted -> run-length accumulate) ----------------
#define POOL_NPB 64
__global__ __launch_bounds__(128) void k_pool(const int* __restrict__ batch, float* __restrict__ out) {
    int c = threadIdx.x;  // one column per thread (128 cols)
    int n0 = blockIdx.x * POOL_NPB;
    int n1 = min(NN, n0 + POOL_NPB);
    float acc = 0.f;
    int gcur = -1, cnt = 0;
    for (int n = n0; n < n1; n++) {
        int g = batch[n];
        if (g != gcur) {
            if (gcur >= 0) {
                atomicAdd(&out[gcur * HIDC + c], acc);
                if (c == 0) atomicAdd(&g_cnt[gcur], (float)cnt);
            }
            acc = 0.f; cnt = 0; gcur = g;
        }
        acc += g_act2[(size_t)n * HIDC + c];
        cnt++;
    }
    if (gcur >= 0) {
        atomicAdd(&out[gcur * HIDC + c], acc);
        if (c == 0) atomicAdd(&g_cnt[gcur], (float)cnt);
    }
}

// ---------------- 12: divide by counts ----------------
__global__ void k_final(float* __restrict__ out) {
    int i = blockIdx.x * blockDim.x + threadIdx.x;
    if (i >= GG * HIDC) return;
    out[i] = out[i] / fmaxf(g_cnt[i >> 7], 1.f);
}

// ---------------- launch ----------------
extern "C" void kernel_launch(void* const* d_in, const int* in_sizes, int n_in,
                              void* d_out, int out_size) {
    const float* x      = (const float*)d_in[0];
    const int*   ei     = (const int*)  d_in[1];
    const int*   batch  = (const int*)  d_in[2];
    const float* W1     = (const float*)d_in[3];
    const float* a_src1 = (const float*)d_in[4];
    const float* a_dst1 = (const float*)d_in[5];
    const float* b1     = (const float*)d_in[6];
    const float* W2     = (const float*)d_in[7];
    const float* a_src2 = (const float*)d_in[8];
    const float* a_dst2 = (const float*)d_in[9];
    const float* b2     = (const float*)d_in[10];
    float* out = (float*)d_out;

    k_zero<<<(GG * HIDC + 255) / 256, 256>>>(out);
    k_hist<<<(ETOT + 255) / 256, 256>>>(ei);
    k_prevec<<<1, 64>>>(W1, a_src1, a_dst1);
    k_alpha1<<<(NN + 255) / 256, 256>>>(x);
    k_scan<<<1, 1024>>>();
    k_scatter<<<(ETOT + 255) / 256, 256>>>(ei);
    k_agg1<<<(NN + 255) / 256, 256>>>(x);
    k_gemm1b<<<(NN + G1B_NPB - 1) / G1B_NPB, 128>>>(W1, b1);
    k_gemm2<<<(NN + 127) / 128, 256>>>(W2);
    k_alpha2<<<(NN * 32 + 255) / 256, 256>>>(a_src2, a_dst2);
    k_agg2<<<(NN * 32 + 255) / 256, 256>>>(b2);
    k_pool<<<(NN + POOL_NPB - 1) / POOL_NPB, 128>>>(batch, out);
    k_final<<<(GG * HIDC + 255) / 256, 256>>>(out);
}

// round 2
// speedup vs baseline: 1.0061x; 1.0061x over previous
#include <cuda_runtime.h>
#include <cstdint>

#define NN   100000
#define EE   300000
#define ETOT 400000   // EE + NN self loops
#define GG   4000
#define INC  9
#define HIDC 128
#define NH   4
#define HC1  512      // NH*HIDC

typedef unsigned long long ull;

// ---------------- scratch (device globals; no allocation allowed) ----------------
__device__ float g_h2  [(size_t)NN * HIDC];  // 51 MB   layer2 pre-agg projection
__device__ float g_act2[(size_t)NN * HIDC];  // 51 MB   elu(layer2 out)
__device__ float g_xagg[(size_t)NN * NH * INC]; // 14.4 MB  per-head alpha-weighted x sums
__device__ float g_as1[NN * NH], g_ad1[NN * NH];
__device__ float g_as2[NN],      g_ad2[NN];
__device__ float g_asv[NH * INC], g_adv[NH * INC]; // projected attention vectors
__device__ int   g_deg[NN];
__device__ int   g_rowoff[NN + 1];
__device__ int   g_cursor[NN];
__device__ int   g_csrc[ETOT];
__device__ float g_cnt[GG];

__device__ __forceinline__ float lrelu(float x) { return x > 0.f ? x : 0.2f * x; }
__device__ __forceinline__ float eluf (float x) { return x > 0.f ? x : expm1f(x); }

// ---------------- 0: zero out + counters ----------------
__global__ void k_zero(float* __restrict__ out) {
    int i = blockIdx.x * blockDim.x + threadIdx.x;
    if (i < GG * HIDC) out[i] = 0.f;
    if (i < NN)        g_deg[i] = 0;
    if (i < GG)        g_cnt[i] = 0.f;
}

// ---------------- 1: dst histogram (edges + self loops) ----------------
__global__ void k_hist(const int* __restrict__ ei) {
    int i = blockIdx.x * blockDim.x + threadIdx.x;
    if (i >= ETOT) return;
    int d = (i < EE) ? ei[EE + i] : (i - EE);
    atomicAdd(&g_deg[d], 1);
}

// ---------------- 2: exclusive scan (single block) ----------------
__global__ void k_scan() {
    const int T = 1024, CH = (NN + T - 1) / T;  // 98
    __shared__ int sh[T];
    int t = threadIdx.x;
    int base = t * CH;
    int s = 0;
    for (int i = 0; i < CH; i++) { int idx = base + i; if (idx < NN) s += g_deg[idx]; }
    sh[t] = s; __syncthreads();
    for (int o = 1; o < T; o <<= 1) {
        int v = (t >= o) ? sh[t - o] : 0;
        __syncthreads();
        sh[t] += v;
        __syncthreads();
    }
    int run = sh[t] - s;  // exclusive
    for (int i = 0; i < CH; i++) {
        int idx = base + i;
        if (idx < NN) { int d = g_deg[idx]; g_rowoff[idx] = run; g_cursor[idx] = run; run += d; }
    }
    if (t == T - 1) g_rowoff[NN] = run;
}

// ---------------- 3: scatter into CSR ----------------
__global__ void k_scatter(const int* __restrict__ ei) {
    int i = blockIdx.x * blockDim.x + threadIdx.x;
    if (i >= ETOT) return;
    int s, d;
    if (i < EE) { s = ei[i]; d = ei[EE + i]; } else { s = d = i - EE; }
    int pos = atomicAdd(&g_cursor[d], 1);
    g_csrc[pos] = s;
}

// ---------------- 4: project attention vectors into input space ----------------
__global__ void k_prevec(const float* __restrict__ W1,
                         const float* __restrict__ a_src1,
                         const float* __restrict__ a_dst1) {
    int t = threadIdx.x;
    if (t >= NH * INC) return;
    int h = t / INC, k = t % INC;
    float s = 0.f, d = 0.f;
    const float* wrow = W1 + k * HC1 + h * HIDC;
    const float* as = a_src1 + h * HIDC;
    const float* ad = a_dst1 + h * HIDC;
    for (int c = 0; c < HIDC; c++) { float w = wrow[c]; s += w * as[c]; d += w * ad[c]; }
    g_asv[t] = s; g_adv[t] = d;
}

// ---------------- 5: per-node attention scalars (layer 1) ----------------
__global__ void k_alpha1(const float* __restrict__ x) {
    int n = blockIdx.x * blockDim.x + threadIdx.x;
    if (n >= NN) return;
    float xr[INC];
#pragma unroll
    for (int k = 0; k < INC; k++) xr[k] = x[n * INC + k];
    float sv[NH], dv[NH];
#pragma unroll
    for (int h = 0; h < NH; h++) {
        float a = 0.f, b = 0.f;
#pragma unroll
        for (int k = 0; k < INC; k++) { a += xr[k] * g_asv[h * INC + k]; b += xr[k] * g_adv[h * INC + k]; }
        sv[h] = a; dv[h] = b;
    }
    *(float4*)&g_as1[n * 4] = make_float4(sv[0], sv[1], sv[2], sv[3]);
    *(float4*)&g_ad1[n * 4] = make_float4(dv[0], dv[1], dv[2], dv[3]);
}

// ---------------- 6: layer-1 aggregation in input space (thread per node) ----------------
__global__ void k_agg1(const float* __restrict__ x) {
    int v = blockIdx.x * blockDim.x + threadIdx.x;
    if (v >= NN) return;
    int e0 = g_rowoff[v], e1 = g_rowoff[v + 1];
    float4 adv = *(const float4*)&g_ad1[v * 4];
    float m[NH] = {-1e30f, -1e30f, -1e30f, -1e30f};
    for (int e = e0; e < e1; e++) {
        int s = g_csrc[e];
        float4 as = *(const float4*)&g_as1[s * 4];
        m[0] = fmaxf(m[0], lrelu(as.x + adv.x)); m[1] = fmaxf(m[1], lrelu(as.y + adv.y));
        m[2] = fmaxf(m[2], lrelu(as.z + adv.z)); m[3] = fmaxf(m[3], lrelu(as.w + adv.w));
    }
    float z[NH] = {0.f, 0.f, 0.f, 0.f};
    float acc[NH][INC];
#pragma unroll
    for (int h = 0; h < NH; h++)
#pragma unroll
        for (int k = 0; k < INC; k++) acc[h][k] = 0.f;
    for (int e = e0; e < e1; e++) {
        int s = g_csrc[e];
        float4 as = *(const float4*)&g_as1[s * 4];
        float w[NH];
        w[0] = __expf(lrelu(as.x + adv.x) - m[0]);
        w[1] = __expf(lrelu(as.y + adv.y) - m[1]);
        w[2] = __expf(lrelu(as.z + adv.z) - m[2]);
        w[3] = __expf(lrelu(as.w + adv.w) - m[3]);
        z[0] += w[0]; z[1] += w[1]; z[2] += w[2]; z[3] += w[3];
        const float* xp = x + (size_t)s * INC;
        float xv[INC];
#pragma unroll
        for (int k = 0; k < INC; k++) xv[k] = __ldg(xp + k);
#pragma unroll
        for (int h = 0; h < NH; h++)
#pragma unroll
            for (int k = 0; k < INC; k++) acc[h][k] += w[h] * xv[k];
    }
#pragma unroll
    for (int h = 0; h < NH; h++) {
        float inv = 1.f / (z[h] + 1e-16f);
#pragma unroll
        for (int k = 0; k < INC; k++) g_xagg[(size_t)v * 36 + h * INC + k] = acc[h][k] * inv;
    }
}

// ---------------- 7: FUSED  h2 = (elu(xagg@W1+b1)) @ W2  + layer-2 alpha epilogue ----------
// Block: 128 rows x 128 cols (full N). K streamed in 4 head-chunks of 128.
// act1 chunk computed on the fly into sA[row][130]; W2 chunk transposed into sBt[col][130].
// Inner loop: k-pair f32x2 FMAs, both operands natural LDS.64 (no dup movs).
#define FUSED_DYN_SMEM (2 * 128 * 130 * 4)

__global__ __launch_bounds__(256) void k_fused(const float* __restrict__ W1,
                                               const float* __restrict__ b1,
                                               const float* __restrict__ W2,
                                               const float* __restrict__ a_src2,
                                               const float* __restrict__ a_dst2) {
    extern __shared__ float dyn[];
    float* sA  = dyn;               // [128][130]  act1 chunk, row-major, pad 130
    float* sBt = dyn + 128 * 130;   // [128][130]  W2 chunk transposed [col][k]
    __shared__ float sX[128 * 12];  // xagg rows for this chunk's head, pad 12
    __shared__ float sU[9 * 128];   // W1 slice [k][col]
    __shared__ float sBias[128];

    int tid = threadIdx.x;
    int tx = tid & 15, ty = tid >> 4;   // col group tx (strided), row group ty
    int bm = blockIdx.x * 128;

    ull acc[8][8];
#pragma unroll
    for (int i = 0; i < 8; i++)
#pragma unroll
        for (int j = 0; j < 8; j++) acc[i][j] = 0ull;

    for (int h = 0; h < NH; h++) {
        __syncthreads();   // previous chunk's MMA done before overwriting tiles
        // stage loads
        for (int idx = tid; idx < 128 * 9; idx += 256) {
            int row = idx / 9, k = idx - row * 9;
            int n = bm + row;
            sX[row * 12 + k] = (n < NN) ? g_xagg[(size_t)n * 36 + h * 9 + k] : 0.f;
        }
        for (int idx = tid; idx < 9 * 128; idx += 256) {
            int k = idx >> 7, c = idx & 127;
            sU[idx] = W1[k * HC1 + h * HIDC + c];
        }
        if (tid < 128) sBias[tid] = b1[h * HIDC + tid];
#pragma unroll
        for (int i = 0; i < 64; i++) {
            int idx = tid + (i << 8);
            int k = idx >> 7, c = idx & 127;
            sBt[c * 130 + k] = W2[(h * HIDC + k) * HIDC + c];
        }
        __syncthreads();
        // compute act1 chunk: thread owns col kk, walks 64 rows
        {
            int kk = tid & 127;
            float w[9];
#pragma unroll
            for (int k = 0; k < 9; k++) w[k] = sU[k * 128 + kk];
            float bb = sBias[kk];
            int rbase = tid >> 7;
#pragma unroll 4
            for (int i = 0; i < 64; i++) {
                int row = rbase + 2 * i;
                float4 x0 = *(const float4*)&sX[row * 12];
                float4 x1 = *(const float4*)&sX[row * 12 + 4];
                float  x8 = sX[row * 12 + 8];
                float a = bb;
                a += x0.x * w[0] + x0.y * w[1] + x0.z * w[2] + x0.w * w[3];
                a += x1.x * w[4] + x1.y * w[5] + x1.z * w[6] + x1.w * w[7];
                a += x8 * w[8];
                sA[row * 130 + kk] = a > 0.f ? a : (__expf(a) - 1.f);
            }
        }
        __syncthreads();
        // MMA: k-pair f32x2
#pragma unroll 2
        for (int kp = 0; kp < 64; kp++) {
            int k = kp * 2;
            ull a2[8], b2[8];
#pragma unroll
            for (int i = 0; i < 8; i++) a2[i] = *(const ull*)&sA[(ty * 8 + i) * 130 + k];
#pragma unroll
            for (int j = 0; j < 8; j++) b2[j] = *(const ull*)&sBt[(tx + 16 * j) * 130 + k];
#pragma unroll
            for (int i = 0; i < 8; i++)
#pragma unroll
                for (int j = 0; j < 8; j++)
                    asm("fma.rn.f32x2 %0, %1, %2, %0;" : "+l"(acc[i][j]) : "l"(a2[i]), "l"(b2[j]));
        }
    }

    // epilogue: reduce k-lanes, store h2, compute layer-2 attention scalars
    float av[8], dv[8];
#pragma unroll
    for (int j = 0; j < 8; j++) { av[j] = a_src2[tx + 16 * j]; dv[j] = a_dst2[tx + 16 * j]; }
#pragma unroll
    for (int i = 0; i < 8; i++) {
        int row = bm + ty * 8 + i;
        float ps = 0.f, pd = 0.f;
        float cv[8];
#pragma unroll
        for (int j = 0; j < 8; j++) {
            union { ull u; float2 f; } c; c.u = acc[i][j];
            float v = c.f.x + c.f.y;
            cv[j] = v;
            ps += v * av[j];
            pd += v * dv[j];
        }
#pragma unroll
        for (int o = 8; o >= 1; o >>= 1) {
            ps += __shfl_xor_sync(0xffffffffu, ps, o, 16);
            pd += __shfl_xor_sync(0xffffffffu, pd, o, 16);
        }
        if (row < NN) {
#pragma unroll
            for (int j = 0; j < 8; j++) g_h2[(size_t)row * HIDC + tx + 16 * j] = cv[j];
            if (tx == 0) { g_as2[row] = ps; g_ad2[row] = pd; }
        }
    }
}

// ---------------- 10: layer-2 aggregation (warp per node) ----------------
__global__ void k_agg2(const float* __restrict__ b2) {
    int v = (blockIdx.x * blockDim.x + threadIdx.x) >> 5;
    int lane = threadIdx.x & 31;
    if (v >= NN) return;
    int e0 = g_rowoff[v], e1 = g_rowoff[v + 1];
    float ad = g_ad2[v];
    float m = -1e30f;
    for (int e = e0; e < e1; e++) {
        int s = g_csrc[e];
        m = fmaxf(m, lrelu(g_as2[s] + ad));
    }
    float z = 0.f;
    float4 acc = make_float4(0.f, 0.f, 0.f, 0.f);
    for (int e = e0; e < e1; e++) {
        int s = g_csrc[e];
        float w = __expf(lrelu(g_as2[s] + ad) - m);
        z += w;
        float4 hv = *(const float4*)&g_h2[(size_t)s * HIDC + lane * 4];
        acc.x += w * hv.x; acc.y += w * hv.y; acc.z += w * hv.z; acc.w += w * hv.w;
    }
    float inv = 1.f / (z + 1e-16f);
    float4 bv = *(const float4*)&b2[lane * 4];
    float4 o;
    o.x = eluf(acc.x * inv + bv.x); o.y = eluf(acc.y * inv + bv.y);
    o.z = eluf(acc.z * inv + bv.z); o.w = eluf(acc.w * inv + bv.w);
    *(float4*)&g_act2[(size_t)v * HIDC + lane * 4] = o;
}

// ---------------- 11: pooled sums (batch sorted -> run-length accumulate) ----------------
#define POOL_NPB 64
__global__ __launch_bounds__(128) void k_pool(const int* __restrict__ batch, float* __restrict__ out) {
    int c = threadIdx.x;
    int n0 = blockIdx.x * POOL_NPB;
    int n1 = min(NN, n0 + POOL_NPB);
    float acc = 0.f;
    int gcur = -1, cnt = 0;
    for (int n = n0; n < n1; n++) {
        int g = batch[n];
        if (g != gcur) {
            if (gcur >= 0) {
                atomicAdd(&out[gcur * HIDC + c], acc);
                if (c == 0) atomicAdd(&g_cnt[gcur], (float)cnt);
            }
            acc = 0.f; cnt = 0; gcur = g;
        }
        acc += g_act2[(size_t)n * HIDC + c];
        cnt++;
    }
    if (gcur >= 0) {
        atomicAdd(&out[gcur * HIDC + c], acc);
        if (c == 0) atomicAdd(&g_cnt[gcur], (float)cnt);
    }
}

// ---------------- 12: divide by counts ----------------
__global__ void k_final(float* __restrict__ out) {
    int i = blockIdx.x * blockDim.x + threadIdx.x;
    if (i >= GG * HIDC) return;
    out[i] = out[i] / fmaxf(g_cnt[i >> 7], 1.f);
}

// ---------------- launch ----------------
extern "C" void kernel_launch(void* const* d_in, const int* in_sizes, int n_in,
                              void* d_out, int out_size) {
    const float* x      = (const float*)d_in[0];
    const int*   ei     = (const int*)  d_in[1];
    const int*   batch  = (const int*)  d_in[2];
    const float* W1     = (const float*)d_in[3];
    const float* a_src1 = (const float*)d_in[4];
    const float* a_dst1 = (const float*)d_in[5];
    const float* b1     = (const float*)d_in[6];
    const float* W2     = (const float*)d_in[7];
    const float* a_src2 = (const float*)d_in[8];
    const float* a_dst2 = (const float*)d_in[9];
    const float* b2     = (const float*)d_in[10];
    float* out = (float*)d_out;

    cudaFuncSetAttribute(k_fused, cudaFuncAttributeMaxDynamicSharedMemorySize, FUSED_DYN_SMEM);

    k_zero<<<(GG * HIDC + 255) / 256, 256>>>(out);
    k_hist<<<(ETOT + 255) / 256, 256>>>(ei);
    k_prevec<<<1, 64>>>(W1, a_src1, a_dst1);
    k_alpha1<<<(NN + 255) / 256, 256>>>(x);
    k_scan<<<1, 1024>>>();
    k_scatter<<<(ETOT + 255) / 256, 256>>>(ei);
    k_agg1<<<(NN + 255) / 256, 256>>>(x);
    k_fused<<<(NN + 127) / 128, 256, FUSED_DYN_SMEM>>>(W1, b1, W2, a_src2, a_dst2);
    k_agg2<<<(NN * 32 + 255) / 256, 256>>>(b2);
    k_pool<<<(NN + POOL_NPB - 1) / POOL_NPB, 128>>>(batch, out);
    k_final<<<(GG * HIDC + 255) / 256, 256>>>(out);
}